// round 1
// baseline (speedup 1.0000x reference)
#include <cuda_runtime.h>
#include <cuda_bf16.h>
#include <float.h>

// Problem constants (from reference setup_inputs)
#define B   256
#define S   512
#define H   768
#define CIT 750
#define XD  1518     // H + CIT
#define D2  3036     // 2*XD
#define NC  6
#define BIGI (S + 1)
#define AT_ID 5
#define CITSEG_ID 7

// ---------------- scratch (static device memory; no allocs allowed) ----------
__device__ int   g_start[B];
__device__ int   g_end[B];
__device__ int   g_cpos[B];
__device__ int   g_hasc[B];
__device__ int   g_keepany[B];
__device__ float g_cith[B * H];      // gathered CITSEG hidden rows
__device__ float g_cit[B * CIT];     // cit projection
__device__ float g_x[B * XD];        // concat(pooled, cit_enc)
__device__ float g_h1[B * D2];
__device__ float g_h2[B * D2];

// ---------------- token scan: one block per batch, 512 threads ---------------
__device__ __forceinline__ int block_min_512(int v, int* sh) {
    int tid = threadIdx.x;
    sh[tid] = v;
    __syncthreads();
    #pragma unroll
    for (int off = 256; off > 0; off >>= 1) {
        if (tid < off) sh[tid] = min(sh[tid], sh[tid + off]);
        __syncthreads();
    }
    int r = sh[0];
    __syncthreads();
    return r;
}

__global__ void scan_kernel(const int* __restrict__ tokens) {
    __shared__ int sh[512];
    int b = blockIdx.x;
    int s = threadIdx.x;
    int t = tokens[b * S + s];
    bool is_at = (t == AT_ID);
    bool is_c  = (t == CITSEG_ID);

    int first  = block_min_512(is_at ? s : BIGI, sh);
    int second = block_min_512((is_at && s > first) ? s : BIGI, sh);
    int cfirst = block_min_512(is_c ? s : BIGI, sh);

    if (threadIdx.x == 0) {
        bool ge2 = (second < BIGI);
        int st = ge2 ? first : 0;
        int en = ge2 ? second : S;
        g_start[b] = st;
        g_end[b]   = en;
        g_keepany[b] = (st > 0) || (en < S - 1);
        g_hasc[b] = (cfirst < BIGI) ? 1 : 0;
        g_cpos[b] = min(cfirst, S - 1);
    }
}

// ---------------- masked max pool -> x[:, 0:H] --------------------------------
__global__ void pool_kernel(const float* __restrict__ hs) {
    int b = blockIdx.y;
    int h = blockIdx.x * 256 + threadIdx.x;   // gridDim.x = H/256 = 3
    int st = g_start[b], en = g_end[b];
    float m = -FLT_MAX;
    const float* base = hs + (size_t)b * S * H + h;
    if (g_keepany[b]) {
        for (int s = 0; s < st; s++)      m = fmaxf(m, base[(size_t)s * H]);
        for (int s = en + 1; s < S; s++)  m = fmaxf(m, base[(size_t)s * H]);
    } else {
        m = 0.f;
    }
    g_x[b * XD + h] = m;
}

// ---------------- gather CITSEG rows ------------------------------------------
__global__ void gather_kernel(const float* __restrict__ hs) {
    int b = blockIdx.y;
    int h = blockIdx.x * 256 + threadIdx.x;   // gridDim.x = 3
    int pos = g_cpos[b];
    g_cith[b * H + h] = hs[(size_t)b * S * H + (size_t)pos * H + h];
}

// ---------------- tiled fp32 GEMM: C = op(A@Bm + bias) ------------------------
// A: [M,K] row-major (lda=K), Bm: [K,N] row-major, C row-major with ldc.
// scale_hasc: if nonzero, multiply output row m by g_hasc[m].
#define BM 64
#define BN 64
#define BK 16
#define TM 4
#define TN 4

__global__ __launch_bounds__(256) void gemm_kernel(
    const float* __restrict__ A, const float* __restrict__ Bm,
    const float* __restrict__ bias, float* __restrict__ C,
    int M, int N, int K, int ldc, int relu, int scale_hasc)
{
    __shared__ float As[BM][BK + 1];
    __shared__ float Bs[BK][BN];

    int tid = threadIdx.x;
    int tx = tid & 15;       // 0..15 -> N
    int ty = tid >> 4;       // 0..15 -> M
    int rowBase = blockIdx.y * BM;
    int colBase = blockIdx.x * BN;

    float acc[TM][TN] = {};

    for (int k0 = 0; k0 < K; k0 += BK) {
        #pragma unroll
        for (int i = 0; i < 4; i++) {
            int idx = tid + i * 256;           // 0..1023
            int m = idx >> 4;                  // /BK
            int k = idx & 15;
            int gm = rowBase + m, gk = k0 + k;
            As[m][k] = (gm < M && gk < K) ? A[(size_t)gm * K + gk] : 0.f;
        }
        #pragma unroll
        for (int i = 0; i < 4; i++) {
            int idx = tid + i * 256;
            int k = idx >> 6;                  // /BN
            int n = idx & 63;
            int gk = k0 + k, gn = colBase + n;
            Bs[k][n] = (gk < K && gn < N) ? Bm[(size_t)gk * N + gn] : 0.f;
        }
        __syncthreads();

        #pragma unroll
        for (int k = 0; k < BK; k++) {
            float a[TM], bb[TN];
            #pragma unroll
            for (int i = 0; i < TM; i++) a[i] = As[ty * TM + i][k];
            #pragma unroll
            for (int j = 0; j < TN; j++) bb[j] = Bs[k][tx * TN + j];
            #pragma unroll
            for (int i = 0; i < TM; i++)
                #pragma unroll
                for (int j = 0; j < TN; j++)
                    acc[i][j] = fmaf(a[i], bb[j], acc[i][j]);
        }
        __syncthreads();
    }

    #pragma unroll
    for (int i = 0; i < TM; i++) {
        int gm = rowBase + ty * TM + i;
        if (gm >= M) continue;
        float sc = scale_hasc ? (float)g_hasc[gm] : 1.f;
        #pragma unroll
        for (int j = 0; j < TN; j++) {
            int gn = colBase + tx * TN + j;
            if (gn >= N) continue;
            float v = (acc[i][j] + bias[gn]) * sc;
            if (relu) v = fmaxf(v, 0.f);
            C[(size_t)gm * ldc + gn] = v;
        }
    }
}

// ---------------- head: out = h2 @ w3 + b3, N=6 -------------------------------
__global__ void head_kernel(const float* __restrict__ w3,
                            const float* __restrict__ b3,
                            float* __restrict__ out)
{
    int b = blockIdx.x;
    int tid = threadIdx.x;  // 256
    float acc[NC] = {};
    for (int k = tid; k < D2; k += 256) {
        float a = g_h2[b * D2 + k];
        #pragma unroll
        for (int n = 0; n < NC; n++) acc[n] = fmaf(a, w3[k * NC + n], acc[n]);
    }
    __shared__ float sh[NC * 256];
    #pragma unroll
    for (int n = 0; n < NC; n++) sh[n * 256 + tid] = acc[n];
    __syncthreads();
    for (int off = 128; off > 0; off >>= 1) {
        if (tid < off) {
            #pragma unroll
            for (int n = 0; n < NC; n++)
                sh[n * 256 + tid] += sh[n * 256 + tid + off];
        }
        __syncthreads();
    }
    if (tid < NC) out[b * NC + tid] = sh[tid * 256] + b3[tid];
}

// ---------------- launch ------------------------------------------------------
extern "C" void kernel_launch(void* const* d_in, const int* in_sizes, int n_in,
                              void* d_out, int out_size)
{
    const int*   tokens = (const int*)  d_in[0];
    const float* hs     = (const float*)d_in[1];
    const float* proj_w = (const float*)d_in[2];
    const float* proj_b = (const float*)d_in[3];
    const float* enc_w  = (const float*)d_in[4];
    const float* enc_b  = (const float*)d_in[5];
    const float* w1     = (const float*)d_in[6];
    const float* b1     = (const float*)d_in[7];
    const float* w2     = (const float*)d_in[8];
    const float* b2     = (const float*)d_in[9];
    const float* w3     = (const float*)d_in[10];
    const float* b3     = (const float*)d_in[11];
    float* out = (float*)d_out;

    float *x, *cith, *cit, *h1, *h2;
    cudaGetSymbolAddress((void**)&x,    g_x);
    cudaGetSymbolAddress((void**)&cith, g_cith);
    cudaGetSymbolAddress((void**)&cit,  g_cit);
    cudaGetSymbolAddress((void**)&h1,   g_h1);
    cudaGetSymbolAddress((void**)&h2,   g_h2);

    // 1. token scan
    scan_kernel<<<B, 512>>>(tokens);

    // 2. masked max-pool -> x[:, 0:H]; gather CITSEG rows (independent)
    pool_kernel<<<dim3(H / 256, B), 256>>>(hs);
    gather_kernel<<<dim3(H / 256, B), 256>>>(hs);

    // 3. cit = (cith @ proj_w + proj_b) * has_c        [256,750], K=768
    gemm_kernel<<<dim3((CIT + BN - 1) / BN, (B + BM - 1) / BM), 256>>>(
        cith, proj_w, proj_b, cit, B, CIT, H, CIT, /*relu=*/0, /*hasc=*/1);

    // 4. cit_enc = cit @ enc_w + enc_b -> x[:, H:XD]   K=750
    gemm_kernel<<<dim3((CIT + BN - 1) / BN, (B + BM - 1) / BM), 256>>>(
        cit, enc_w, enc_b, x + H, B, CIT, CIT, XD, 0, 0);

    // 5. h1 = relu(x @ w1 + b1)                        [256,3036], K=1518
    gemm_kernel<<<dim3((D2 + BN - 1) / BN, (B + BM - 1) / BM), 256>>>(
        x, w1, b1, h1, B, D2, XD, D2, 1, 0);

    // 6. h2 = relu(h1 @ w2 + b2)                       [256,3036], K=3036
    gemm_kernel<<<dim3((D2 + BN - 1) / BN, (B + BM - 1) / BM), 256>>>(
        h1, w2, b2, h2, B, D2, D2, D2, 1, 0);

    // 7. out = h2 @ w3 + b3                            [256,6]
    head_kernel<<<B, 256>>>(w3, b3, out);
}

// round 2
// speedup vs baseline: 1.4211x; 1.4211x over previous
#include <cuda_runtime.h>
#include <cuda_bf16.h>
#include <float.h>
#include <stdint.h>

// Problem constants
#define B   256
#define S   512
#define H   768
#define CIT 750
#define XD  1518     // H + CIT
#define D2  3036     // 2*XD
#define NC  6
#define BIGI (S + 1)
#define AT_ID 5
#define CITSEG_ID 7

// ---------------- scratch ------------------------------------------------------
__device__ int   g_start[B];
__device__ int   g_end[B];
__device__ int   g_cpos[B];
__device__ int   g_hasc[B];
__device__ int   g_keepany[B];
__device__ float g_cith[B * H];
__device__ float g_cit[B * CIT];
__device__ float g_x[B * XD];
__device__ float g_h1[B * D2];
__device__ float g_h2[B * D2];

// ---------------- token scan ----------------------------------------------------
__device__ __forceinline__ int block_min_512(int v, int* sh) {
    int tid = threadIdx.x;
    sh[tid] = v;
    __syncthreads();
    #pragma unroll
    for (int off = 256; off > 0; off >>= 1) {
        if (tid < off) sh[tid] = min(sh[tid], sh[tid + off]);
        __syncthreads();
    }
    int r = sh[0];
    __syncthreads();
    return r;
}

__global__ void scan_kernel(const int* __restrict__ tokens) {
    __shared__ int sh[512];
    int b = blockIdx.x;
    int s = threadIdx.x;
    int t = tokens[b * S + s];
    bool is_at = (t == AT_ID);
    bool is_c  = (t == CITSEG_ID);

    int first  = block_min_512(is_at ? s : BIGI, sh);
    int second = block_min_512((is_at && s > first) ? s : BIGI, sh);
    int cfirst = block_min_512(is_c ? s : BIGI, sh);

    if (threadIdx.x == 0) {
        bool ge2 = (second < BIGI);
        int st = ge2 ? first : 0;
        int en = ge2 ? second : S;
        g_start[b] = st;
        g_end[b]   = en;
        g_keepany[b] = (st > 0) || (en < S - 1);
        g_hasc[b] = (cfirst < BIGI) ? 1 : 0;
        g_cpos[b] = min(cfirst, S - 1);
    }
}

// ---------------- masked max pool -> x[:, 0:H] -----------------------------------
__global__ void pool_kernel(const float* __restrict__ hs) {
    int b = blockIdx.y;
    int h = blockIdx.x * 256 + threadIdx.x;
    int st = g_start[b], en = g_end[b];
    const float* base = hs + (size_t)b * S * H + h;
    float m = -FLT_MAX;
    if (g_keepany[b]) {
        float m0 = -FLT_MAX, m1 = -FLT_MAX, m2 = -FLT_MAX, m3 = -FLT_MAX;
        int s = 0;
        for (; s + 4 <= st; s += 4) {
            m0 = fmaxf(m0, base[(size_t)(s    ) * H]);
            m1 = fmaxf(m1, base[(size_t)(s + 1) * H]);
            m2 = fmaxf(m2, base[(size_t)(s + 2) * H]);
            m3 = fmaxf(m3, base[(size_t)(s + 3) * H]);
        }
        for (; s < st; s++) m0 = fmaxf(m0, base[(size_t)s * H]);
        s = en + 1;
        for (; s + 4 <= S; s += 4) {
            m0 = fmaxf(m0, base[(size_t)(s    ) * H]);
            m1 = fmaxf(m1, base[(size_t)(s + 1) * H]);
            m2 = fmaxf(m2, base[(size_t)(s + 2) * H]);
            m3 = fmaxf(m3, base[(size_t)(s + 3) * H]);
        }
        for (; s < S; s++) m0 = fmaxf(m0, base[(size_t)s * H]);
        m = fmaxf(fmaxf(m0, m1), fmaxf(m2, m3));
    } else {
        m = 0.f;
    }
    g_x[b * XD + h] = m;
}

// ---------------- gather CITSEG rows ----------------------------------------------
__global__ void gather_kernel(const float* __restrict__ hs) {
    int b = blockIdx.y;
    int h = blockIdx.x * 256 + threadIdx.x;
    int pos = g_cpos[b];
    g_cith[b * H + h] = hs[(size_t)b * S * H + (size_t)pos * H + h];
}

// ---------------- split-bf16 tensor-core GEMM -------------------------------------
// C[M,N] = op(A[M,K] @ Bm[K,N] + bias), fp32 in/out, split-bf16 MMA internally.
// A*B ~= Ahi*Bhi + Ahi*Blo + Alo*Bhi  (effective ~15 mantissa bits)
#define BM 64
#define BN 128
#define BK 32
#define BKP (BK + 2)   // padded (bf16 elems) -> row stride 68B, conflict-free

#define MMA_BF16(d, a, b) \
  asm volatile("mma.sync.aligned.m16n8k16.row.col.f32.bf16.bf16.f32 " \
    "{%0,%1,%2,%3}, {%4,%5,%6,%7}, {%8,%9}, {%0,%1,%2,%3};" \
    : "+f"(d[0]), "+f"(d[1]), "+f"(d[2]), "+f"(d[3]) \
    : "r"(a[0]), "r"(a[1]), "r"(a[2]), "r"(a[3]), "r"(b[0]), "r"(b[1]))

__global__ __launch_bounds__(256) void gemm_tc_kernel(
    const float* __restrict__ A, const float* __restrict__ Bm,
    const float* __restrict__ bias, float* __restrict__ C,
    int M, int N, int K, int ldc, int relu, int scale_hasc)
{
    __shared__ __nv_bfloat16 Ahi[BM][BKP], Alo[BM][BKP];
    __shared__ __nv_bfloat16 Bhi[BN][BKP], Blo[BN][BKP];

    int tid  = threadIdx.x;
    int lane = tid & 31;
    int warp = tid >> 5;          // 0..7
    int warpM = warp >> 2;        // 0..1 -> 32-row slab
    int warpN = warp & 3;         // 0..3 -> 32-col slab
    int g = lane >> 2;            // 0..7
    int t = lane & 3;             // 0..3

    int rowBase = blockIdx.y * BM;
    int colBase = blockIdx.x * BN;

    float acc[2][4][4] = {};      // [mtile 16][ntile 8][frag]

    for (int k0 = 0; k0 < K; k0 += BK) {
        // load A tile 64x32 fp32 -> split bf16 (coalesced: 1 row / warp)
        {
            int k = tid & 31;
            int mrow = tid >> 5;
            #pragma unroll
            for (int i = 0; i < 8; i++) {
                int m = mrow + i * 8;
                int gm = rowBase + m, gk = k0 + k;
                float v = (gm < M && gk < K) ? A[(size_t)gm * K + gk] : 0.f;
                __nv_bfloat16 hi = __float2bfloat16(v);
                __nv_bfloat16 lo = __float2bfloat16(v - __bfloat162float(hi));
                Ahi[m][k] = hi;
                Alo[m][k] = lo;
            }
        }
        // load B tile 32x128 fp32 -> transpose to [n][k], split bf16
        {
            int n = tid & 127;
            int krow = tid >> 7;          // 0..1
            #pragma unroll
            for (int i = 0; i < 16; i++) {
                int k = krow + i * 2;
                int gk = k0 + k, gn = colBase + n;
                float v = (gk < K && gn < N) ? Bm[(size_t)gk * N + gn] : 0.f;
                __nv_bfloat16 hi = __float2bfloat16(v);
                __nv_bfloat16 lo = __float2bfloat16(v - __bfloat162float(hi));
                Bhi[n][k] = hi;
                Blo[n][k] = lo;
            }
        }
        __syncthreads();

        #pragma unroll
        for (int ks = 0; ks < BK; ks += 16) {
            uint32_t ahi[2][4], alo[2][4], bhi[4][2], blo[4][2];
            #pragma unroll
            for (int mi = 0; mi < 2; mi++) {
                int r = warpM * 32 + mi * 16 + g;
                ahi[mi][0] = *(const uint32_t*)&Ahi[r    ][ks + 2 * t];
                ahi[mi][1] = *(const uint32_t*)&Ahi[r + 8][ks + 2 * t];
                ahi[mi][2] = *(const uint32_t*)&Ahi[r    ][ks + 2 * t + 8];
                ahi[mi][3] = *(const uint32_t*)&Ahi[r + 8][ks + 2 * t + 8];
                alo[mi][0] = *(const uint32_t*)&Alo[r    ][ks + 2 * t];
                alo[mi][1] = *(const uint32_t*)&Alo[r + 8][ks + 2 * t];
                alo[mi][2] = *(const uint32_t*)&Alo[r    ][ks + 2 * t + 8];
                alo[mi][3] = *(const uint32_t*)&Alo[r + 8][ks + 2 * t + 8];
            }
            #pragma unroll
            for (int ni = 0; ni < 4; ni++) {
                int n = warpN * 32 + ni * 8 + g;
                bhi[ni][0] = *(const uint32_t*)&Bhi[n][ks + 2 * t];
                bhi[ni][1] = *(const uint32_t*)&Bhi[n][ks + 2 * t + 8];
                blo[ni][0] = *(const uint32_t*)&Blo[n][ks + 2 * t];
                blo[ni][1] = *(const uint32_t*)&Blo[n][ks + 2 * t + 8];
            }
            #pragma unroll
            for (int mi = 0; mi < 2; mi++)
                #pragma unroll
                for (int ni = 0; ni < 4; ni++) {
                    MMA_BF16(acc[mi][ni], ahi[mi], bhi[ni]);
                    MMA_BF16(acc[mi][ni], ahi[mi], blo[ni]);
                    MMA_BF16(acc[mi][ni], alo[mi], bhi[ni]);
                }
        }
        __syncthreads();
    }

    // epilogue
    #pragma unroll
    for (int mi = 0; mi < 2; mi++) {
        int r0 = rowBase + warpM * 32 + mi * 16 + g;
        #pragma unroll
        for (int ni = 0; ni < 4; ni++) {
            int c0 = colBase + warpN * 32 + ni * 8 + 2 * t;
            #pragma unroll
            for (int f = 0; f < 4; f++) {
                int gm = r0 + (f >= 2 ? 8 : 0);
                int gn = c0 + (f & 1);
                if (gm < M && gn < N) {
                    float sc = scale_hasc ? (float)g_hasc[gm] : 1.f;
                    float v = (acc[mi][ni][f] + bias[gn]) * sc;
                    if (relu) v = fmaxf(v, 0.f);
                    C[(size_t)gm * ldc + gn] = v;
                }
            }
        }
    }
}

// ---------------- head: out = h2 @ w3 + b3, N=6 ------------------------------------
__global__ void head_kernel(const float* __restrict__ w3,
                            const float* __restrict__ b3,
                            float* __restrict__ out)
{
    int b = blockIdx.x;
    int tid = threadIdx.x;  // 256
    float acc[NC] = {};
    for (int k = tid; k < D2; k += 256) {
        float a = g_h2[b * D2 + k];
        #pragma unroll
        for (int n = 0; n < NC; n++) acc[n] = fmaf(a, w3[k * NC + n], acc[n]);
    }
    __shared__ float sh[NC * 256];
    #pragma unroll
    for (int n = 0; n < NC; n++) sh[n * 256 + tid] = acc[n];
    __syncthreads();
    for (int off = 128; off > 0; off >>= 1) {
        if (tid < off) {
            #pragma unroll
            for (int n = 0; n < NC; n++)
                sh[n * 256 + tid] += sh[n * 256 + tid + off];
        }
        __syncthreads();
    }
    if (tid < NC) out[b * NC + tid] = sh[tid * 256] + b3[tid];
}

// ---------------- launch -------------------------------------------------------------
extern "C" void kernel_launch(void* const* d_in, const int* in_sizes, int n_in,
                              void* d_out, int out_size)
{
    const int*   tokens = (const int*)  d_in[0];
    const float* hs     = (const float*)d_in[1];
    const float* proj_w = (const float*)d_in[2];
    const float* proj_b = (const float*)d_in[3];
    const float* enc_w  = (const float*)d_in[4];
    const float* enc_b  = (const float*)d_in[5];
    const float* w1     = (const float*)d_in[6];
    const float* b1     = (const float*)d_in[7];
    const float* w2     = (const float*)d_in[8];
    const float* b2     = (const float*)d_in[9];
    const float* w3     = (const float*)d_in[10];
    const float* b3     = (const float*)d_in[11];
    float* out = (float*)d_out;

    float *x, *cith, *cit, *h1, *h2;
    cudaGetSymbolAddress((void**)&x,    g_x);
    cudaGetSymbolAddress((void**)&cith, g_cith);
    cudaGetSymbolAddress((void**)&cit,  g_cit);
    cudaGetSymbolAddress((void**)&h1,   g_h1);
    cudaGetSymbolAddress((void**)&h2,   g_h2);

    scan_kernel<<<B, 512>>>(tokens);

    pool_kernel<<<dim3(H / 256, B), 256>>>(hs);
    gather_kernel<<<dim3(H / 256, B), 256>>>(hs);

    // cit = (cith @ proj_w + proj_b) * has_c     [256,750], K=768
    gemm_tc_kernel<<<dim3((CIT + BN - 1) / BN, (B + BM - 1) / BM), 256>>>(
        cith, proj_w, proj_b, cit, B, CIT, H, CIT, 0, 1);

    // cit_enc = cit @ enc_w + enc_b -> x[:, H:]  K=750
    gemm_tc_kernel<<<dim3((CIT + BN - 1) / BN, (B + BM - 1) / BM), 256>>>(
        cit, enc_w, enc_b, x + H, B, CIT, CIT, XD, 0, 0);

    // h1 = relu(x @ w1 + b1)                     [256,3036], K=1518
    gemm_tc_kernel<<<dim3((D2 + BN - 1) / BN, (B + BM - 1) / BM), 256>>>(
        x, w1, b1, h1, B, D2, XD, D2, 1, 0);

    // h2 = relu(h1 @ w2 + b2)                    [256,3036], K=3036
    gemm_tc_kernel<<<dim3((D2 + BN - 1) / BN, (B + BM - 1) / BM), 256>>>(
        h1, w2, b2, h2, B, D2, D2, D2, 1, 0);

    head_kernel<<<B, 256>>>(w3, b3, out);
}

// round 3
// speedup vs baseline: 1.8152x; 1.2773x over previous
#include <cuda_runtime.h>
#include <cuda_bf16.h>
#include <float.h>
#include <stdint.h>

// Problem constants
#define B   256
#define S   512
#define H   768
#define CIT 750
#define XD  1518     // H + CIT
#define D2  3036     // 2*XD
#define NC  6
#define BIGI (S + 1)
#define AT_ID 5
#define CITSEG_ID 7

// Padded dims (K to %32, N to %64)
#define KP_H    768    // H
#define KP_CIT  768    // CIT padded
#define KP_X    1536   // XD padded
#define KP_D2   3072   // D2 padded
#define NP_CIT  768
#define NP_D2   3072

// ---------------- scratch ------------------------------------------------------
__device__ int   g_start[B];
__device__ int   g_end[B];
__device__ int   g_cpos[B];
__device__ int   g_hasc[B];
__device__ int   g_keepany[B];

// transposed + split weights: [Npad][Kpad] bf16 hi/lo
__device__ __nv_bfloat16 g_projwt_hi[NP_CIT * KP_H],  g_projwt_lo[NP_CIT * KP_H];
__device__ __nv_bfloat16 g_encwt_hi [NP_CIT * KP_CIT], g_encwt_lo [NP_CIT * KP_CIT];
__device__ __nv_bfloat16 g_w1t_hi  [NP_D2 * KP_X],   g_w1t_lo  [NP_D2 * KP_X];
__device__ __nv_bfloat16 g_w2t_hi  [NP_D2 * KP_D2],  g_w2t_lo  [NP_D2 * KP_D2];

// split activations: [256][Kpad]
__device__ __nv_bfloat16 g_cith_hi[B * KP_H],  g_cith_lo[B * KP_H];
__device__ __nv_bfloat16 g_cit_hi [B * KP_CIT], g_cit_lo [B * KP_CIT];
__device__ __nv_bfloat16 g_x_hi  [B * KP_X],   g_x_lo  [B * KP_X];
__device__ __nv_bfloat16 g_h1_hi [B * KP_D2],  g_h1_lo [B * KP_D2];
__device__ float g_h2[B * D2];

// ---------------- helpers -------------------------------------------------------
__device__ __forceinline__ uint32_t smem_u32(const void* p) {
    return (uint32_t)__cvta_generic_to_shared(p);
}
#define CP_ASYNC16(dst_u32, src) \
    asm volatile("cp.async.cg.shared.global [%0], [%1], 16;\n" :: "r"(dst_u32), "l"(src))
#define CP_COMMIT() asm volatile("cp.async.commit_group;\n")
#define CP_WAIT1()  asm volatile("cp.async.wait_group 1;\n")

__device__ __forceinline__ void split_bf16(float v, __nv_bfloat16& hi, __nv_bfloat16& lo) {
    hi = __float2bfloat16(v);
    lo = __float2bfloat16(v - __bfloat162float(hi));
}

// ---------------- token scan ----------------------------------------------------
__device__ __forceinline__ int block_min_512(int v, int* sh) {
    int tid = threadIdx.x;
    sh[tid] = v;
    __syncthreads();
    #pragma unroll
    for (int off = 256; off > 0; off >>= 1) {
        if (tid < off) sh[tid] = min(sh[tid], sh[tid + off]);
        __syncthreads();
    }
    int r = sh[0];
    __syncthreads();
    return r;
}

__global__ void scan_kernel(const int* __restrict__ tokens) {
    __shared__ int sh[512];
    int b = blockIdx.x;
    int s = threadIdx.x;
    int t = tokens[b * S + s];
    bool is_at = (t == AT_ID);
    bool is_c  = (t == CITSEG_ID);

    int first  = block_min_512(is_at ? s : BIGI, sh);
    int second = block_min_512((is_at && s > first) ? s : BIGI, sh);
    int cfirst = block_min_512(is_c ? s : BIGI, sh);

    if (threadIdx.x == 0) {
        bool ge2 = (second < BIGI);
        int st = ge2 ? first : 0;
        int en = ge2 ? second : S;
        g_start[b] = st;
        g_end[b]   = en;
        g_keepany[b] = (st > 0) || (en < S - 1);
        g_hasc[b] = (cfirst < BIGI) ? 1 : 0;
        g_cpos[b] = min(cfirst, S - 1);
    }
}

// ---------------- masked max pool -> x_hi/lo[:, 0:H] ------------------------------
__global__ void pool_kernel(const float* __restrict__ hs) {
    int b = blockIdx.y;
    int h = blockIdx.x * 256 + threadIdx.x;
    int st = g_start[b], en = g_end[b];
    const float* base = hs + (size_t)b * S * H + h;
    float m;
    if (g_keepany[b]) {
        float m0 = -FLT_MAX, m1 = -FLT_MAX, m2 = -FLT_MAX, m3 = -FLT_MAX;
        int s = 0;
        for (; s + 4 <= st; s += 4) {
            m0 = fmaxf(m0, base[(size_t)(s    ) * H]);
            m1 = fmaxf(m1, base[(size_t)(s + 1) * H]);
            m2 = fmaxf(m2, base[(size_t)(s + 2) * H]);
            m3 = fmaxf(m3, base[(size_t)(s + 3) * H]);
        }
        for (; s < st; s++) m0 = fmaxf(m0, base[(size_t)s * H]);
        s = en + 1;
        for (; s + 4 <= S; s += 4) {
            m0 = fmaxf(m0, base[(size_t)(s    ) * H]);
            m1 = fmaxf(m1, base[(size_t)(s + 1) * H]);
            m2 = fmaxf(m2, base[(size_t)(s + 2) * H]);
            m3 = fmaxf(m3, base[(size_t)(s + 3) * H]);
        }
        for (; s < S; s++) m0 = fmaxf(m0, base[(size_t)s * H]);
        m = fmaxf(fmaxf(m0, m1), fmaxf(m2, m3));
    } else {
        m = 0.f;
    }
    __nv_bfloat16 hi, lo;
    split_bf16(m, hi, lo);
    g_x_hi[b * KP_X + h] = hi;
    g_x_lo[b * KP_X + h] = lo;
}

// ---------------- gather CITSEG rows -> cith hi/lo ---------------------------------
__global__ void gather_kernel(const float* __restrict__ hs) {
    int b = blockIdx.y;
    int h = blockIdx.x * 256 + threadIdx.x;
    int pos = g_cpos[b];
    float v = hs[(size_t)b * S * H + (size_t)pos * H + h];
    __nv_bfloat16 hi, lo;
    split_bf16(v, hi, lo);
    g_cith_hi[b * KP_H + h] = hi;
    g_cith_lo[b * KP_H + h] = lo;
}

// ---------------- zero padding columns of activation buffers -----------------------
__global__ void pad_zero_kernel() {
    int b = blockIdx.x;
    int t = threadIdx.x;  // 64
    __nv_bfloat16 z = __float2bfloat16(0.f);
    for (int c = t; c < KP_CIT - CIT; c += 64) {           // 18
        g_cit_hi[b * KP_CIT + CIT + c] = z;
        g_cit_lo[b * KP_CIT + CIT + c] = z;
    }
    for (int c = t; c < KP_X - XD; c += 64) {              // 18
        g_x_hi[b * KP_X + XD + c] = z;
        g_x_lo[b * KP_X + XD + c] = z;
    }
    for (int c = t; c < KP_D2 - D2; c += 64) {             // 36
        g_h1_hi[b * KP_D2 + D2 + c] = z;
        g_h1_lo[b * KP_D2 + D2 + c] = z;
    }
}

// ---------------- weight transpose + split convert ---------------------------------
// W [K,N] fp32 -> Thi/Tlo [Npad][Kpad] bf16, zero-filled in pads.
__global__ void transpose_convert_kernel(const float* __restrict__ W,
                                         __nv_bfloat16* __restrict__ Thi,
                                         __nv_bfloat16* __restrict__ Tlo,
                                         int K, int N, int Kpad)
{
    __shared__ float tile[32][33];
    int k0 = blockIdx.y * 32;
    int n0 = blockIdx.x * 32;
    int tx = threadIdx.x;       // 32
    int ty = threadIdx.y;       // 8
    #pragma unroll
    for (int i = 0; i < 4; i++) {
        int ky = ty + i * 8;
        int gk = k0 + ky, gn = n0 + tx;
        tile[ky][tx] = (gk < K && gn < N) ? W[(size_t)gk * N + gn] : 0.f;
    }
    __syncthreads();
    #pragma unroll
    for (int i = 0; i < 4; i++) {
        int ny = ty + i * 8;
        int gn = n0 + ny, gk = k0 + tx;
        float v = tile[tx][ny];
        __nv_bfloat16 hi, lo;
        split_bf16(v, hi, lo);
        Thi[(size_t)gn * Kpad + gk] = hi;
        Tlo[(size_t)gn * Kpad + gk] = lo;
    }
}

// ---------------- split-bf16 tensor-core GEMM, cp.async double-buffered ------------
// A hi/lo: [256][Kp] bf16 (padded, zeros beyond real K)
// B hi/lo: [Npad][Kp] bf16 (transposed weights, zero pads)
// C = op(A@B^T + bias); optional fp32 out and/or bf16 hi/lo out.
#define BM 64
#define BN 64
#define BK 32
#define BKP 40    // padded k stride (80B rows: 16B aligned, conflict-staggered)

#define MMA_BF16(d, a, b) \
  asm volatile("mma.sync.aligned.m16n8k16.row.col.f32.bf16.bf16.f32 " \
    "{%0,%1,%2,%3}, {%4,%5,%6,%7}, {%8,%9}, {%0,%1,%2,%3};" \
    : "+f"(d[0]), "+f"(d[1]), "+f"(d[2]), "+f"(d[3]) \
    : "r"(a[0]), "r"(a[1]), "r"(a[2]), "r"(a[3]), "r"(b[0]), "r"(b[1]))

__global__ __launch_bounds__(256) void gemm_bf16_kernel(
    const __nv_bfloat16* __restrict__ Ah, const __nv_bfloat16* __restrict__ Al, int Kp,
    const __nv_bfloat16* __restrict__ Bh, const __nv_bfloat16* __restrict__ Bl,
    const float* __restrict__ bias, int N,
    float* Cf, int ldc,
    __nv_bfloat16* Ch, __nv_bfloat16* Cl, int ldcp,
    int relu, int scale_hasc)
{
    __shared__ __nv_bfloat16 sAh[2][BM][BKP], sAl[2][BM][BKP];
    __shared__ __nv_bfloat16 sBh[2][BN][BKP], sBl[2][BN][BKP];

    int tid  = threadIdx.x;
    int lane = tid & 31;
    int warp = tid >> 5;          // 0..7
    int warpM = warp >> 2;        // 0..1 -> 32-row slab
    int warpN = warp & 3;         // 0..3 -> 16-col slab
    int g = lane >> 2;
    int t = lane & 3;

    int rowBase = blockIdx.y * BM;   // M=256, grid.y=4 -> always in-bounds
    int colBase = blockIdx.x * BN;   // covers Npad -> B loads in-bounds

    // cp.async mapping: one 16B chunk per thread per plane
    int ldRow = tid >> 2;            // 0..63
    int ldCol = (tid & 3) * 8;       // 0,8,16,24 (bf16 elems)

    const __nv_bfloat16* pAh = Ah + (size_t)(rowBase + ldRow) * Kp + ldCol;
    const __nv_bfloat16* pAl = Al + (size_t)(rowBase + ldRow) * Kp + ldCol;
    const __nv_bfloat16* pBh = Bh + (size_t)(colBase + ldRow) * Kp + ldCol;
    const __nv_bfloat16* pBl = Bl + (size_t)(colBase + ldRow) * Kp + ldCol;

    uint32_t dAh[2], dAl[2], dBh[2], dBl[2];
    #pragma unroll
    for (int s2 = 0; s2 < 2; s2++) {
        dAh[s2] = smem_u32(&sAh[s2][ldRow][ldCol]);
        dAl[s2] = smem_u32(&sAl[s2][ldRow][ldCol]);
        dBh[s2] = smem_u32(&sBh[s2][ldRow][ldCol]);
        dBl[s2] = smem_u32(&sBl[s2][ldRow][ldCol]);
    }

    float acc[2][2][4] = {};

    int nk = Kp / BK;
    // prologue: stage 0
    CP_ASYNC16(dAh[0], pAh);
    CP_ASYNC16(dAl[0], pAl);
    CP_ASYNC16(dBh[0], pBh);
    CP_ASYNC16(dBl[0], pBl);
    CP_COMMIT();

    for (int it = 0; it < nk; it++) {
        int cur = it & 1;
        if (it + 1 < nk) {
            int nxt = cur ^ 1;
            size_t off = (size_t)(it + 1) * BK;
            CP_ASYNC16(dAh[nxt], pAh + off);
            CP_ASYNC16(dAl[nxt], pAl + off);
            CP_ASYNC16(dBh[nxt], pBh + off);
            CP_ASYNC16(dBl[nxt], pBl + off);
        }
        CP_COMMIT();
        CP_WAIT1();
        __syncthreads();

        #pragma unroll
        for (int ks = 0; ks < BK; ks += 16) {
            uint32_t ahi[2][4], alo[2][4], bhi[2][2], blo[2][2];
            #pragma unroll
            for (int mi = 0; mi < 2; mi++) {
                int r = warpM * 32 + mi * 16 + g;
                ahi[mi][0] = *(const uint32_t*)&sAh[cur][r    ][ks + 2 * t];
                ahi[mi][1] = *(const uint32_t*)&sAh[cur][r + 8][ks + 2 * t];
                ahi[mi][2] = *(const uint32_t*)&sAh[cur][r    ][ks + 2 * t + 8];
                ahi[mi][3] = *(const uint32_t*)&sAh[cur][r + 8][ks + 2 * t + 8];
                alo[mi][0] = *(const uint32_t*)&sAl[cur][r    ][ks + 2 * t];
                alo[mi][1] = *(const uint32_t*)&sAl[cur][r + 8][ks + 2 * t];
                alo[mi][2] = *(const uint32_t*)&sAl[cur][r    ][ks + 2 * t + 8];
                alo[mi][3] = *(const uint32_t*)&sAl[cur][r + 8][ks + 2 * t + 8];
            }
            #pragma unroll
            for (int ni = 0; ni < 2; ni++) {
                int n = warpN * 16 + ni * 8 + g;
                bhi[ni][0] = *(const uint32_t*)&sBh[cur][n][ks + 2 * t];
                bhi[ni][1] = *(const uint32_t*)&sBh[cur][n][ks + 2 * t + 8];
                blo[ni][0] = *(const uint32_t*)&sBl[cur][n][ks + 2 * t];
                blo[ni][1] = *(const uint32_t*)&sBl[cur][n][ks + 2 * t + 8];
            }
            #pragma unroll
            for (int mi = 0; mi < 2; mi++)
                #pragma unroll
                for (int ni = 0; ni < 2; ni++) {
                    MMA_BF16(acc[mi][ni], ahi[mi], bhi[ni]);
                    MMA_BF16(acc[mi][ni], ahi[mi], blo[ni]);
                    MMA_BF16(acc[mi][ni], alo[mi], bhi[ni]);
                }
        }
        __syncthreads();
    }

    // epilogue
    #pragma unroll
    for (int mi = 0; mi < 2; mi++) {
        #pragma unroll
        for (int ni = 0; ni < 2; ni++) {
            #pragma unroll
            for (int f = 0; f < 4; f++) {
                int gm = rowBase + warpM * 32 + mi * 16 + g + (f >= 2 ? 8 : 0);
                int gn = colBase + warpN * 16 + ni * 8 + 2 * t + (f & 1);
                if (gn < N) {
                    float sc = scale_hasc ? (float)g_hasc[gm] : 1.f;
                    float v = (acc[mi][ni][f] + bias[gn]) * sc;
                    if (relu) v = fmaxf(v, 0.f);
                    if (Cf) Cf[(size_t)gm * ldc + gn] = v;
                    if (Ch) {
                        __nv_bfloat16 hi, lo;
                        split_bf16(v, hi, lo);
                        Ch[(size_t)gm * ldcp + gn] = hi;
                        Cl[(size_t)gm * ldcp + gn] = lo;
                    }
                }
            }
        }
    }
}

// ---------------- head: out = h2 @ w3 + b3, N=6 ------------------------------------
__global__ void head_kernel(const float* __restrict__ w3,
                            const float* __restrict__ b3,
                            float* __restrict__ out)
{
    int b = blockIdx.x;
    int tid = threadIdx.x;  // 256
    float acc[NC] = {};
    for (int k = tid; k < D2; k += 256) {
        float a = g_h2[b * D2 + k];
        #pragma unroll
        for (int n = 0; n < NC; n++) acc[n] = fmaf(a, w3[k * NC + n], acc[n]);
    }
    __shared__ float sh[NC * 256];
    #pragma unroll
    for (int n = 0; n < NC; n++) sh[n * 256 + tid] = acc[n];
    __syncthreads();
    for (int off = 128; off > 0; off >>= 1) {
        if (tid < off) {
            #pragma unroll
            for (int n = 0; n < NC; n++)
                sh[n * 256 + tid] += sh[n * 256 + tid + off];
        }
        __syncthreads();
    }
    if (tid < NC) out[b * NC + tid] = sh[tid * 256] + b3[tid];
}

// ---------------- launch -------------------------------------------------------------
extern "C" void kernel_launch(void* const* d_in, const int* in_sizes, int n_in,
                              void* d_out, int out_size)
{
    const int*   tokens = (const int*)  d_in[0];
    const float* hs     = (const float*)d_in[1];
    const float* proj_w = (const float*)d_in[2];
    const float* proj_b = (const float*)d_in[3];
    const float* enc_w  = (const float*)d_in[4];
    const float* enc_b  = (const float*)d_in[5];
    const float* w1     = (const float*)d_in[6];
    const float* b1     = (const float*)d_in[7];
    const float* w2     = (const float*)d_in[8];
    const float* b2     = (const float*)d_in[9];
    const float* w3     = (const float*)d_in[10];
    const float* b3     = (const float*)d_in[11];
    float* out = (float*)d_out;

    // resolve device symbols
    __nv_bfloat16 *projwt_h, *projwt_l, *encwt_h, *encwt_l, *w1t_h, *w1t_l, *w2t_h, *w2t_l;
    __nv_bfloat16 *cith_h, *cith_l, *cit_h, *cit_l, *x_h, *x_l, *h1_h, *h1_l;
    float* h2;
    cudaGetSymbolAddress((void**)&projwt_h, g_projwt_hi);
    cudaGetSymbolAddress((void**)&projwt_l, g_projwt_lo);
    cudaGetSymbolAddress((void**)&encwt_h,  g_encwt_hi);
    cudaGetSymbolAddress((void**)&encwt_l,  g_encwt_lo);
    cudaGetSymbolAddress((void**)&w1t_h,    g_w1t_hi);
    cudaGetSymbolAddress((void**)&w1t_l,    g_w1t_lo);
    cudaGetSymbolAddress((void**)&w2t_h,    g_w2t_hi);
    cudaGetSymbolAddress((void**)&w2t_l,    g_w2t_lo);
    cudaGetSymbolAddress((void**)&cith_h,   g_cith_hi);
    cudaGetSymbolAddress((void**)&cith_l,   g_cith_lo);
    cudaGetSymbolAddress((void**)&cit_h,    g_cit_hi);
    cudaGetSymbolAddress((void**)&cit_l,    g_cit_lo);
    cudaGetSymbolAddress((void**)&x_h,      g_x_hi);
    cudaGetSymbolAddress((void**)&x_l,      g_x_lo);
    cudaGetSymbolAddress((void**)&h1_h,     g_h1_hi);
    cudaGetSymbolAddress((void**)&h1_l,     g_h1_lo);
    cudaGetSymbolAddress((void**)&h2,       g_h2);

    dim3 tb(32, 8);

    // weight transposes (independent of everything else)
    transpose_convert_kernel<<<dim3(NP_CIT / 32, KP_H / 32), tb>>>(proj_w, projwt_h, projwt_l, H, CIT, KP_H);
    transpose_convert_kernel<<<dim3(NP_CIT / 32, KP_CIT / 32), tb>>>(enc_w, encwt_h, encwt_l, CIT, CIT, KP_CIT);
    transpose_convert_kernel<<<dim3(NP_D2 / 32, KP_X / 32), tb>>>(w1, w1t_h, w1t_l, XD, D2, KP_X);
    transpose_convert_kernel<<<dim3(NP_D2 / 32, KP_D2 / 32), tb>>>(w2, w2t_h, w2t_l, D2, D2, KP_D2);

    scan_kernel<<<B, 512>>>(tokens);
    pad_zero_kernel<<<B, 64>>>();

    pool_kernel<<<dim3(H / 256, B), 256>>>(hs);
    gather_kernel<<<dim3(H / 256, B), 256>>>(hs);

    // gemm1: cit = (cith @ proj_w + proj_b) * has_c    [256,750] K=768
    gemm_bf16_kernel<<<dim3(NP_CIT / BN, B / BM), 256>>>(
        cith_h, cith_l, KP_H, projwt_h, projwt_l, proj_b, CIT,
        nullptr, 0, cit_h, cit_l, KP_CIT, 0, 1);

    // gemm2: x[:, H:] = cit @ enc_w + enc_b            [256,750] K=750(pad 768)
    gemm_bf16_kernel<<<dim3(NP_CIT / BN, B / BM), 256>>>(
        cit_h, cit_l, KP_CIT, encwt_h, encwt_l, enc_b, CIT,
        nullptr, 0, x_h + H, x_l + H, KP_X, 0, 0);

    // gemm3: h1 = relu(x @ w1 + b1)                    [256,3036] K=1518(pad 1536)
    gemm_bf16_kernel<<<dim3(NP_D2 / BN, B / BM), 256>>>(
        x_h, x_l, KP_X, w1t_h, w1t_l, b1, D2,
        nullptr, 0, h1_h, h1_l, KP_D2, 1, 0);

    // gemm4: h2 = relu(h1 @ w2 + b2)                   [256,3036] K=3036(pad 3072)
    gemm_bf16_kernel<<<dim3(NP_D2 / BN, B / BM), 256>>>(
        h1_h, h1_l, KP_D2, w2t_h, w2t_l, b2, D2,
        h2, D2, nullptr, nullptr, 0, 1, 0);

    head_kernel<<<B, 256>>>(w3, b3, out);
}

// round 4
// speedup vs baseline: 2.0484x; 1.1284x over previous
#include <cuda_runtime.h>
#include <cuda_bf16.h>
#include <float.h>
#include <stdint.h>

#define B   256
#define S   512
#define H   768
#define CIT 750
#define XD  1518
#define D2  3036
#define NC  6
#define BIGI (S + 1)
#define AT_ID 5
#define CITSEG_ID 7

// padded dims
#define KP_H    768
#define KP_CIT  768
#define KP_X    1536
#define KP_D2   3072
#define NP_CIT  768
#define NP_D2   3072

// ---------------- scratch ------------------------------------------------------
__device__ int   g_start[B];
__device__ int   g_end[B];
__device__ int   g_cpos[B];
__device__ int   g_hasc[B];
__device__ int   g_keepany[B];

// converted weights, natural [Kpad][Npad] layout, bf16 hi/lo planes
__device__ __nv_bfloat16 g_projw_hi[KP_H  * NP_CIT], g_projw_lo[KP_H  * NP_CIT];
__device__ __nv_bfloat16 g_encw_hi [KP_CIT* NP_CIT], g_encw_lo [KP_CIT* NP_CIT];
__device__ __nv_bfloat16 g_w1_hi  [KP_X  * NP_D2],  g_w1_lo  [KP_X  * NP_D2];
__device__ __nv_bfloat16 g_w2_hi  [KP_D2 * NP_D2],  g_w2_lo  [KP_D2 * NP_D2];

// split activations: [256][Kpad]
__device__ __nv_bfloat16 g_cith_hi[B * KP_H],   g_cith_lo[B * KP_H];
__device__ __nv_bfloat16 g_cit_hi [B * KP_CIT], g_cit_lo [B * KP_CIT];
__device__ __nv_bfloat16 g_x_hi  [B * KP_X],    g_x_lo  [B * KP_X];
__device__ __nv_bfloat16 g_h1_hi [B * KP_D2],   g_h1_lo [B * KP_D2];
__device__ float g_h2[B * D2];

// ---------------- helpers -------------------------------------------------------
__device__ __forceinline__ uint32_t smem_u32(const void* p) {
    return (uint32_t)__cvta_generic_to_shared(p);
}
#define CP_ASYNC16(dst_u32, src) \
    asm volatile("cp.async.cg.shared.global [%0], [%1], 16;\n" :: "r"(dst_u32), "l"(src))
#define CP_COMMIT() asm volatile("cp.async.commit_group;\n")
#define CP_WAIT1()  asm volatile("cp.async.wait_group 1;\n")

#define LDSM_X4(R, addr) \
    asm volatile("ldmatrix.sync.aligned.m8n8.x4.shared.b16 {%0,%1,%2,%3}, [%4];" \
      : "=r"((R)[0]), "=r"((R)[1]), "=r"((R)[2]), "=r"((R)[3]) : "r"(addr))
#define LDSM_X4_T(R, addr) \
    asm volatile("ldmatrix.sync.aligned.m8n8.x4.trans.shared.b16 {%0,%1,%2,%3}, [%4];" \
      : "=r"((R)[0]), "=r"((R)[1]), "=r"((R)[2]), "=r"((R)[3]) : "r"(addr))

#define MMA_BF16(d, a, b0, b1) \
  asm volatile("mma.sync.aligned.m16n8k16.row.col.f32.bf16.bf16.f32 " \
    "{%0,%1,%2,%3}, {%4,%5,%6,%7}, {%8,%9}, {%0,%1,%2,%3};" \
    : "+f"((d)[0]), "+f"((d)[1]), "+f"((d)[2]), "+f"((d)[3]) \
    : "r"((a)[0]), "r"((a)[1]), "r"((a)[2]), "r"((a)[3]), "r"(b0), "r"(b1))

__device__ __forceinline__ void split_bf16(float v, __nv_bfloat16& hi, __nv_bfloat16& lo) {
    hi = __float2bfloat16(v);
    lo = __float2bfloat16(v - __bfloat162float(hi));
}

// ---------------- token scan ----------------------------------------------------
__device__ __forceinline__ int block_min_512(int v, int* sh) {
    int tid = threadIdx.x;
    sh[tid] = v;
    __syncthreads();
    #pragma unroll
    for (int off = 256; off > 0; off >>= 1) {
        if (tid < off) sh[tid] = min(sh[tid], sh[tid + off]);
        __syncthreads();
    }
    int r = sh[0];
    __syncthreads();
    return r;
}

__global__ void scan_kernel(const int* __restrict__ tokens) {
    __shared__ int sh[512];
    int b = blockIdx.x;
    int s = threadIdx.x;
    int t = tokens[b * S + s];
    bool is_at = (t == AT_ID);
    bool is_c  = (t == CITSEG_ID);

    int first  = block_min_512(is_at ? s : BIGI, sh);
    int second = block_min_512((is_at && s > first) ? s : BIGI, sh);
    int cfirst = block_min_512(is_c ? s : BIGI, sh);

    if (threadIdx.x == 0) {
        bool ge2 = (second < BIGI);
        int st = ge2 ? first : 0;
        int en = ge2 ? second : S;
        g_start[b] = st;
        g_end[b]   = en;
        g_keepany[b] = (st > 0) || (en < S - 1);
        g_hasc[b] = (cfirst < BIGI) ? 1 : 0;
        g_cpos[b] = min(cfirst, S - 1);
    }
}

// ---------------- fused pool + gather (float4, 192 thr = 768 cols) ----------------
__device__ __forceinline__ float4 fmax4(float4 a, float4 b) {
    return make_float4(fmaxf(a.x, b.x), fmaxf(a.y, b.y), fmaxf(a.z, b.z), fmaxf(a.w, b.w));
}

__global__ __launch_bounds__(192) void pool_gather_kernel(const float* __restrict__ hs) {
    int b = blockIdx.x;
    int t = threadIdx.x;            // 0..191, covers 4 h-cols each
    const float4* base = (const float4*)(hs + (size_t)b * S * H);  // row = s*192 + t

    int st = g_start[b], en = g_end[b];
    float4 m;
    if (g_keepany[b]) {
        float4 m0 = make_float4(-FLT_MAX, -FLT_MAX, -FLT_MAX, -FLT_MAX);
        float4 m1 = m0;
        int s = 0;
        for (; s + 2 <= st; s += 2) {
            m0 = fmax4(m0, base[(size_t)(s    ) * 192 + t]);
            m1 = fmax4(m1, base[(size_t)(s + 1) * 192 + t]);
        }
        for (; s < st; s++) m0 = fmax4(m0, base[(size_t)s * 192 + t]);
        s = en + 1;
        for (; s + 2 <= S; s += 2) {
            m0 = fmax4(m0, base[(size_t)(s    ) * 192 + t]);
            m1 = fmax4(m1, base[(size_t)(s + 1) * 192 + t]);
        }
        for (; s < S; s++) m0 = fmax4(m0, base[(size_t)s * 192 + t]);
        m = fmax4(m0, m1);
    } else {
        m = make_float4(0.f, 0.f, 0.f, 0.f);
    }
    {
        int h = t * 4;
        float mv[4] = {m.x, m.y, m.z, m.w};
        #pragma unroll
        for (int j = 0; j < 4; j++) {
            __nv_bfloat16 hi, lo;
            split_bf16(mv[j], hi, lo);
            g_x_hi[b * KP_X + h + j] = hi;
            g_x_lo[b * KP_X + h + j] = lo;
        }
    }
    // gather CITSEG row
    {
        float4 c = base[(size_t)g_cpos[b] * 192 + t];
        float cv[4] = {c.x, c.y, c.z, c.w};
        int h = t * 4;
        #pragma unroll
        for (int j = 0; j < 4; j++) {
            __nv_bfloat16 hi, lo;
            split_bf16(cv[j], hi, lo);
            g_cith_hi[b * KP_H + h + j] = hi;
            g_cith_lo[b * KP_H + h + j] = lo;
        }
    }
}

// ---------------- zero padding columns of activation buffers -----------------------
__global__ void pad_zero_kernel() {
    int b = blockIdx.x;
    int t = threadIdx.x;  // 64
    __nv_bfloat16 z = __float2bfloat16(0.f);
    for (int c = t; c < KP_CIT - CIT; c += 64) {
        g_cit_hi[b * KP_CIT + CIT + c] = z;
        g_cit_lo[b * KP_CIT + CIT + c] = z;
    }
    for (int c = t; c < KP_X - XD; c += 64) {
        g_x_hi[b * KP_X + XD + c] = z;
        g_x_lo[b * KP_X + XD + c] = z;
    }
    for (int c = t; c < KP_D2 - D2; c += 64) {
        g_h1_hi[b * KP_D2 + D2 + c] = z;
        g_h1_lo[b * KP_D2 + D2 + c] = z;
    }
}

// ---------------- weight convert (no transpose): W[K,N] fp32 -> [Kpad][Npad] hi/lo --
__global__ void convert_pad_kernel(const float* __restrict__ W,
                                   __nv_bfloat16* __restrict__ Oh,
                                   __nv_bfloat16* __restrict__ Ol,
                                   int K, int N, int Npad, int total4)
{
    int idx = blockIdx.x * 256 + threadIdx.x;
    if (idx >= total4) return;
    int npc = Npad >> 2;
    int k  = idx / npc;
    int nc = (idx - k * npc) << 2;
    float v[4];
    if (k < K && nc + 3 < N) {
        const float* p = W + (size_t)k * N + nc;
        v[0] = p[0]; v[1] = p[1]; v[2] = p[2]; v[3] = p[3];
    } else {
        #pragma unroll
        for (int j = 0; j < 4; j++)
            v[j] = (k < K && nc + j < N) ? W[(size_t)k * N + nc + j] : 0.f;
    }
    __nv_bfloat16 hi[4], lo[4];
    #pragma unroll
    for (int j = 0; j < 4; j++) split_bf16(v[j], hi[j], lo[j]);
    size_t o = (size_t)k * Npad + nc;
    *(__nv_bfloat162*)(Oh + o)     = *(__nv_bfloat162*)&hi[0];
    *(__nv_bfloat162*)(Oh + o + 2) = *(__nv_bfloat162*)&hi[2];
    *(__nv_bfloat162*)(Ol + o)     = *(__nv_bfloat162*)&lo[0];
    *(__nv_bfloat162*)(Ol + o + 2) = *(__nv_bfloat162*)&lo[2];
}

// ---------------- split-bf16 ldmatrix GEMM ------------------------------------------
// A hi/lo [256][Kp] row-major; B hi/lo [Kp][Np] row-major. C = op(A@B + bias).
#define BM 64
#define BN 64
#define BK 64
#define BKP 72   // 144B row stride: conflict-free for ldmatrix
#define BNP 72

#define SA_ELEMS (2 * 64 * BKP)   // per plane, 2 stages
#define SB_ELEMS (2 * 64 * BNP)
#define GEMM_SMEM_BYTES ((SA_ELEMS * 2 + SB_ELEMS * 2) * 2)

__global__ __launch_bounds__(256, 2) void gemm_bf16_kernel(
    const __nv_bfloat16* __restrict__ Ah, const __nv_bfloat16* __restrict__ Al, int Kp,
    const __nv_bfloat16* __restrict__ Bh, const __nv_bfloat16* __restrict__ Bl, int Np,
    const float* __restrict__ bias, int N,
    float* Cf, int ldc,
    __nv_bfloat16* Ch, __nv_bfloat16* Cl, int ldcp,
    int relu, int scale_hasc)
{
    extern __shared__ __nv_bfloat16 sm[];
    __nv_bfloat16* sAh = sm;
    __nv_bfloat16* sAl = sAh + SA_ELEMS;
    __nv_bfloat16* sBh = sAl + SA_ELEMS;
    __nv_bfloat16* sBl = sBh + SB_ELEMS;

    int tid  = threadIdx.x;
    int lane = tid & 31;
    int warp = tid >> 5;
    int warpM = warp >> 2;        // 0..1 -> 32 rows
    int warpN = warp & 3;         // 0..3 -> 16 cols
    int g = lane >> 2;
    int t = lane & 3;

    int rowBase = blockIdx.y * BM;
    int colBase = blockIdx.x * BN;

    // cp.async mapping: 512 16B-chunks per 64x128B tile; 2 per thread per plane
    int ldRow0 = tid >> 3;                 // 0..31
    int ldCol  = (tid & 7) * 8;            // bf16 elems
    const __nv_bfloat16* pAh = Ah + (size_t)(rowBase + ldRow0) * Kp + ldCol;
    const __nv_bfloat16* pAl = Al + (size_t)(rowBase + ldRow0) * Kp + ldCol;
    const __nv_bfloat16* pBh = Bh + (size_t)ldRow0 * Np + colBase + ldCol;
    const __nv_bfloat16* pBl = Bl + (size_t)ldRow0 * Np + colBase + ldCol;
    size_t aRowStep = (size_t)32 * Kp;
    size_t bRowStep = (size_t)32 * Np;

    uint32_t base_u32 = smem_u32(sm);
    uint32_t dA = base_u32 + (ldRow0 * BKP + ldCol) * 2;
    uint32_t dB = base_u32 + (SA_ELEMS * 2 + SB_ELEMS * 0) * 0; // placeholder
    uint32_t offAl = SA_ELEMS * 2;           // bytes: SA_ELEMS elems *2B
    uint32_t offBh = SA_ELEMS * 4;
    uint32_t offBl = SA_ELEMS * 4 + SB_ELEMS * 2;
    uint32_t dAh0 = base_u32 + (ldRow0 * BKP + ldCol) * 2;
    uint32_t dB0  = base_u32 + offBh + (ldRow0 * BNP + ldCol) * 2;

    float acc[2][2][4] = {};

    int nk = Kp / BK;

    // prologue: stage 0
    {
        #pragma unroll
        for (int i = 0; i < 2; i++) {
            uint32_t sa = dAh0 + i * 32 * BKP * 2;
            uint32_t sb = dB0  + i * 32 * BNP * 2;
            CP_ASYNC16(sa,          pAh + i * aRowStep);
            CP_ASYNC16(sa + offAl,  pAl + i * aRowStep);
            CP_ASYNC16(sb,          pBh + i * bRowStep);
            CP_ASYNC16(sb + (SB_ELEMS * 2), pBl + i * bRowStep);
        }
    }
    CP_COMMIT();

    for (int it = 0; it < nk; it++) {
        int cur = it & 1;
        if (it + 1 < nk) {
            int nxt = cur ^ 1;
            size_t ka = (size_t)(it + 1) * BK;
            uint32_t stA = nxt * 64 * BKP * 2;
            uint32_t stB = nxt * 64 * BNP * 2;
            #pragma unroll
            for (int i = 0; i < 2; i++) {
                uint32_t sa = dAh0 + stA + i * 32 * BKP * 2;
                uint32_t sb = dB0  + stB + i * 32 * BNP * 2;
                CP_ASYNC16(sa,          pAh + ka + i * aRowStep);
                CP_ASYNC16(sa + offAl,  pAl + ka + i * aRowStep);
                CP_ASYNC16(sb,          pBh + ka * Np + i * bRowStep);
                CP_ASYNC16(sb + (SB_ELEMS * 2), pBl + ka * Np + i * bRowStep);
            }
        }
        CP_COMMIT();
        CP_WAIT1();
        __syncthreads();

        uint32_t stA = cur * 64 * BKP * 2;
        uint32_t stB = cur * 64 * BNP * 2;

        #pragma unroll
        for (int ks = 0; ks < BK; ks += 16) {
            uint32_t ahi[2][4], alo[2][4], bhi[4], blo[4];
            // A fragments: ldmatrix.x4, addr = &sA[r0 + (lane&15)][ks + (lane>>4)*8]
            #pragma unroll
            for (int mi = 0; mi < 2; mi++) {
                int arow = warpM * 32 + mi * 16 + (lane & 15);
                int acol = ks + (lane >> 4) * 8;
                uint32_t ea = stA + (arow * BKP + acol) * 2;
                LDSM_X4(ahi[mi], base_u32 + ea);
                LDSM_X4(alo[mi], base_u32 + offAl + ea);
            }
            // B fragments: ldmatrix.x4.trans from [k][n]
            {
                int mm = lane >> 3;                       // 0..3
                int krow = ks + (mm & 1) * 8 + (lane & 7);
                int ncol = warpN * 16 + (mm >> 1) * 8;
                uint32_t eb = stB + (krow * BNP + ncol) * 2;
                LDSM_X4_T(bhi, base_u32 + offBh + eb);
                LDSM_X4_T(blo, base_u32 + offBl + eb);
            }
            #pragma unroll
            for (int mi = 0; mi < 2; mi++) {
                MMA_BF16(acc[mi][0], ahi[mi], bhi[0], bhi[1]);
                MMA_BF16(acc[mi][0], ahi[mi], blo[0], blo[1]);
                MMA_BF16(acc[mi][0], alo[mi], bhi[0], bhi[1]);
                MMA_BF16(acc[mi][1], ahi[mi], bhi[2], bhi[3]);
                MMA_BF16(acc[mi][1], ahi[mi], blo[2], blo[3]);
                MMA_BF16(acc[mi][1], alo[mi], bhi[2], bhi[3]);
            }
        }
        __syncthreads();
    }

    // epilogue
    #pragma unroll
    for (int mi = 0; mi < 2; mi++) {
        #pragma unroll
        for (int ni = 0; ni < 2; ni++) {
            #pragma unroll
            for (int f = 0; f < 4; f++) {
                int gm = rowBase + warpM * 32 + mi * 16 + g + (f >= 2 ? 8 : 0);
                int gn = colBase + warpN * 16 + ni * 8 + 2 * t + (f & 1);
                if (gn < N) {
                    float sc = scale_hasc ? (float)g_hasc[gm] : 1.f;
                    float v = (acc[mi][ni][f] + bias[gn]) * sc;
                    if (relu) v = fmaxf(v, 0.f);
                    if (Cf) Cf[(size_t)gm * ldc + gn] = v;
                    if (Ch) {
                        __nv_bfloat16 hi, lo;
                        split_bf16(v, hi, lo);
                        Ch[(size_t)gm * ldcp + gn] = hi;
                        Cl[(size_t)gm * ldcp + gn] = lo;
                    }
                }
            }
        }
    }
}

// ---------------- head: out = h2 @ w3 + b3, N=6 ------------------------------------
__global__ void head_kernel(const float* __restrict__ w3,
                            const float* __restrict__ b3,
                            float* __restrict__ out)
{
    int b = blockIdx.x;
    int tid = threadIdx.x;  // 256
    float acc[NC] = {};
    for (int k = tid; k < D2; k += 256) {
        float a = g_h2[b * D2 + k];
        #pragma unroll
        for (int n = 0; n < NC; n++) acc[n] = fmaf(a, w3[k * NC + n], acc[n]);
    }
    __shared__ float sh[NC * 256];
    #pragma unroll
    for (int n = 0; n < NC; n++) sh[n * 256 + tid] = acc[n];
    __syncthreads();
    for (int off = 128; off > 0; off >>= 1) {
        if (tid < off) {
            #pragma unroll
            for (int n = 0; n < NC; n++)
                sh[n * 256 + tid] += sh[n * 256 + tid + off];
        }
        __syncthreads();
    }
    if (tid < NC) out[b * NC + tid] = sh[tid * 256] + b3[tid];
}

// ---------------- launch -------------------------------------------------------------
extern "C" void kernel_launch(void* const* d_in, const int* in_sizes, int n_in,
                              void* d_out, int out_size)
{
    const int*   tokens = (const int*)  d_in[0];
    const float* hs     = (const float*)d_in[1];
    const float* proj_w = (const float*)d_in[2];
    const float* proj_b = (const float*)d_in[3];
    const float* enc_w  = (const float*)d_in[4];
    const float* enc_b  = (const float*)d_in[5];
    const float* w1     = (const float*)d_in[6];
    const float* b1     = (const float*)d_in[7];
    const float* w2     = (const float*)d_in[8];
    const float* b2     = (const float*)d_in[9];
    const float* w3     = (const float*)d_in[10];
    const float* b3     = (const float*)d_in[11];
    float* out = (float*)d_out;

    __nv_bfloat16 *projw_h, *projw_l, *encw_h, *encw_l, *w1_h, *w1_l, *w2_h, *w2_l;
    __nv_bfloat16 *cith_h, *cith_l, *cit_h, *cit_l, *x_h, *x_l, *h1_h, *h1_l;
    float* h2;
    cudaGetSymbolAddress((void**)&projw_h, g_projw_hi);
    cudaGetSymbolAddress((void**)&projw_l, g_projw_lo);
    cudaGetSymbolAddress((void**)&encw_h,  g_encw_hi);
    cudaGetSymbolAddress((void**)&encw_l,  g_encw_lo);
    cudaGetSymbolAddress((void**)&w1_h,    g_w1_hi);
    cudaGetSymbolAddress((void**)&w1_l,    g_w1_lo);
    cudaGetSymbolAddress((void**)&w2_h,    g_w2_hi);
    cudaGetSymbolAddress((void**)&w2_l,    g_w2_lo);
    cudaGetSymbolAddress((void**)&cith_h,  g_cith_hi);
    cudaGetSymbolAddress((void**)&cith_l,  g_cith_lo);
    cudaGetSymbolAddress((void**)&cit_h,   g_cit_hi);
    cudaGetSymbolAddress((void**)&cit_l,   g_cit_lo);
    cudaGetSymbolAddress((void**)&x_h,     g_x_hi);
    cudaGetSymbolAddress((void**)&x_l,     g_x_lo);
    cudaGetSymbolAddress((void**)&h1_h,    g_h1_hi);
    cudaGetSymbolAddress((void**)&h1_l,    g_h1_lo);
    cudaGetSymbolAddress((void**)&h2,      g_h2);

    static bool attr_set = false;
    if (!attr_set) {
        cudaFuncSetAttribute(gemm_bf16_kernel,
                             cudaFuncAttributeMaxDynamicSharedMemorySize, GEMM_SMEM_BYTES);
        attr_set = true;
    }

    // weight converts (independent)
    {
        int t4 = KP_H * NP_CIT / 4;
        convert_pad_kernel<<<(t4 + 255) / 256, 256>>>(proj_w, projw_h, projw_l, H, CIT, NP_CIT, t4);
        t4 = KP_CIT * NP_CIT / 4;
        convert_pad_kernel<<<(t4 + 255) / 256, 256>>>(enc_w, encw_h, encw_l, CIT, CIT, NP_CIT, t4);
        t4 = KP_X * NP_D2 / 4;
        convert_pad_kernel<<<(t4 + 255) / 256, 256>>>(w1, w1_h, w1_l, XD, D2, NP_D2, t4);
        t4 = KP_D2 * NP_D2 / 4;
        convert_pad_kernel<<<(t4 + 255) / 256, 256>>>(w2, w2_h, w2_l, D2, D2, NP_D2, t4);
    }

    scan_kernel<<<B, 512>>>(tokens);
    pad_zero_kernel<<<B, 64>>>();
    pool_gather_kernel<<<B, 192>>>(hs);

    // gemm1: cit = (cith @ proj_w + proj_b) * has_c    [256,750] K=768
    gemm_bf16_kernel<<<dim3(NP_CIT / BN, B / BM), 256, GEMM_SMEM_BYTES>>>(
        cith_h, cith_l, KP_H, projw_h, projw_l, NP_CIT, proj_b, CIT,
        nullptr, 0, cit_h, cit_l, KP_CIT, 0, 1);

    // gemm2: x[:, H:] = cit @ enc_w + enc_b            [256,750] K=768(pad)
    gemm_bf16_kernel<<<dim3(NP_CIT / BN, B / BM), 256, GEMM_SMEM_BYTES>>>(
        cit_h, cit_l, KP_CIT, encw_h, encw_l, NP_CIT, enc_b, CIT,
        nullptr, 0, x_h + H, x_l + H, KP_X, 0, 0);

    // gemm3: h1 = relu(x @ w1 + b1)                    [256,3036] K=1536(pad)
    gemm_bf16_kernel<<<dim3(NP_D2 / BN, B / BM), 256, GEMM_SMEM_BYTES>>>(
        x_h, x_l, KP_X, w1_h, w1_l, NP_D2, b1, D2,
        nullptr, 0, h1_h, h1_l, KP_D2, 1, 0);

    // gemm4: h2 = relu(h1 @ w2 + b2)                   [256,3036] K=3072(pad)
    gemm_bf16_kernel<<<dim3(NP_D2 / BN, B / BM), 256, GEMM_SMEM_BYTES>>>(
        h1_h, h1_l, KP_D2, w2_h, w2_l, NP_D2, b2, D2,
        h2, D2, nullptr, nullptr, 0, 1, 0);

    head_kernel<<<B, 256>>>(w3, b3, out);
}

// round 5
// speedup vs baseline: 2.3614x; 1.1528x over previous
#include <cuda_runtime.h>
#include <cuda_bf16.h>
#include <float.h>
#include <stdint.h>

#define B   256
#define S   512
#define H   768
#define CIT 750
#define XD  1518
#define D2  3036
#define NC  6
#define BIGI (S + 1)
#define AT_ID 5
#define CITSEG_ID 7

// padded dims
#define KP_H    768
#define KP_CIT  768
#define KP_X    1536
#define KP_D2   3072
#define NP_CIT  768
#define NP_D2   3072

#define PCH 8            // pool S-chunks
#define CHS (S / PCH)    // 64 rows per chunk

// ---------------- scratch ------------------------------------------------------
__device__ int   g_start[B];
__device__ int   g_end[B];
__device__ int   g_cpos[B];
__device__ int   g_hasc[B];
__device__ int   g_keepany[B];
__device__ float g_pmax[B * PCH * H];   // pool partials

// converted weights, natural [Kpad][Npad] layout, bf16 hi/lo planes
__device__ __nv_bfloat16 g_projw_hi[KP_H  * NP_CIT], g_projw_lo[KP_H  * NP_CIT];
__device__ __nv_bfloat16 g_encw_hi [KP_CIT* NP_CIT], g_encw_lo [KP_CIT* NP_CIT];
__device__ __nv_bfloat16 g_w1_hi  [KP_X  * NP_D2],  g_w1_lo  [KP_X  * NP_D2];
__device__ __nv_bfloat16 g_w2_hi  [KP_D2 * NP_D2],  g_w2_lo  [KP_D2 * NP_D2];

// split activations: [256][Kpad]
__device__ __nv_bfloat16 g_cith_hi[B * KP_H],   g_cith_lo[B * KP_H];
__device__ __nv_bfloat16 g_cit_hi [B * KP_CIT], g_cit_lo [B * KP_CIT];
__device__ __nv_bfloat16 g_x_hi  [B * KP_X],    g_x_lo  [B * KP_X];
__device__ __nv_bfloat16 g_h1_hi [B * KP_D2],   g_h1_lo [B * KP_D2];
__device__ float g_h2[B * D2];

// ---------------- helpers -------------------------------------------------------
__device__ __forceinline__ uint32_t smem_u32(const void* p) {
    return (uint32_t)__cvta_generic_to_shared(p);
}
#define CP_ASYNC16(dst_u32, src) \
    asm volatile("cp.async.cg.shared.global [%0], [%1], 16;\n" :: "r"(dst_u32), "l"(src))
#define CP_COMMIT() asm volatile("cp.async.commit_group;\n")
#define CP_WAIT1()  asm volatile("cp.async.wait_group 1;\n")

#define LDSM_X4(R, addr) \
    asm volatile("ldmatrix.sync.aligned.m8n8.x4.shared.b16 {%0,%1,%2,%3}, [%4];" \
      : "=r"((R)[0]), "=r"((R)[1]), "=r"((R)[2]), "=r"((R)[3]) : "r"(addr))
#define LDSM_X4_T(R, addr) \
    asm volatile("ldmatrix.sync.aligned.m8n8.x4.trans.shared.b16 {%0,%1,%2,%3}, [%4];" \
      : "=r"((R)[0]), "=r"((R)[1]), "=r"((R)[2]), "=r"((R)[3]) : "r"(addr))

#define MMA_BF16(d, a, b0, b1) \
  asm volatile("mma.sync.aligned.m16n8k16.row.col.f32.bf16.bf16.f32 " \
    "{%0,%1,%2,%3}, {%4,%5,%6,%7}, {%8,%9}, {%0,%1,%2,%3};" \
    : "+f"((d)[0]), "+f"((d)[1]), "+f"((d)[2]), "+f"((d)[3]) \
    : "r"((a)[0]), "r"((a)[1]), "r"((a)[2]), "r"((a)[3]), "r"(b0), "r"(b1))

__device__ __forceinline__ void split_bf16(float v, __nv_bfloat16& hi, __nv_bfloat16& lo) {
    hi = __float2bfloat16(v);
    lo = __float2bfloat16(v - __bfloat162float(hi));
}

__device__ __forceinline__ float4 fmax4(float4 a, float4 b) {
    return make_float4(fmaxf(a.x, b.x), fmaxf(a.y, b.y), fmaxf(a.z, b.z), fmaxf(a.w, b.w));
}

// ---------------- token scan ----------------------------------------------------
__device__ __forceinline__ int block_min_512(int v, int* sh) {
    int tid = threadIdx.x;
    sh[tid] = v;
    __syncthreads();
    #pragma unroll
    for (int off = 256; off > 0; off >>= 1) {
        if (tid < off) sh[tid] = min(sh[tid], sh[tid + off]);
        __syncthreads();
    }
    int r = sh[0];
    __syncthreads();
    return r;
}

__global__ void scan_kernel(const int* __restrict__ tokens) {
    __shared__ int sh[512];
    int b = blockIdx.x;
    int s = threadIdx.x;
    int t = tokens[b * S + s];
    bool is_at = (t == AT_ID);
    bool is_c  = (t == CITSEG_ID);

    int first  = block_min_512(is_at ? s : BIGI, sh);
    int second = block_min_512((is_at && s > first) ? s : BIGI, sh);
    int cfirst = block_min_512(is_c ? s : BIGI, sh);

    if (threadIdx.x == 0) {
        bool ge2 = (second < BIGI);
        int st = ge2 ? first : 0;
        int en = ge2 ? second : S;
        g_start[b] = st;
        g_end[b]   = en;
        g_keepany[b] = (st > 0) || (en < S - 1);
        g_hasc[b] = (cfirst < BIGI) ? 1 : 0;
        g_cpos[b] = min(cfirst, S - 1);
    }
}

// ---------------- pool pass 1: per-chunk partial max (grid B x PCH) ----------------
__global__ __launch_bounds__(192) void pool_partial_kernel(const float* __restrict__ hs) {
    int b = blockIdx.x;
    int c = blockIdx.y;
    int t = threadIdx.x;
    int st = g_start[b], en = g_end[b];
    const float4* base = (const float4*)(hs + (size_t)b * S * H);

    int s0 = c * CHS, s1 = s0 + CHS;
    float4 m0 = make_float4(-FLT_MAX, -FLT_MAX, -FLT_MAX, -FLT_MAX);
    float4 m1 = m0, m2 = m0, m3 = m0;

    // range [s0, min(s1, st))
    int aEnd = min(s1, st);
    int s = s0;
    for (; s + 4 <= aEnd; s += 4) {
        m0 = fmax4(m0, base[(size_t)(s    ) * 192 + t]);
        m1 = fmax4(m1, base[(size_t)(s + 1) * 192 + t]);
        m2 = fmax4(m2, base[(size_t)(s + 2) * 192 + t]);
        m3 = fmax4(m3, base[(size_t)(s + 3) * 192 + t]);
    }
    for (; s < aEnd; s++) m0 = fmax4(m0, base[(size_t)s * 192 + t]);

    // range [max(s0, en+1), s1)
    s = max(s0, en + 1);
    for (; s + 4 <= s1; s += 4) {
        m0 = fmax4(m0, base[(size_t)(s    ) * 192 + t]);
        m1 = fmax4(m1, base[(size_t)(s + 1) * 192 + t]);
        m2 = fmax4(m2, base[(size_t)(s + 2) * 192 + t]);
        m3 = fmax4(m3, base[(size_t)(s + 3) * 192 + t]);
    }
    for (; s < s1; s++) m0 = fmax4(m0, base[(size_t)s * 192 + t]);

    float4 m = fmax4(fmax4(m0, m1), fmax4(m2, m3));
    ((float4*)g_pmax)[(size_t)(b * PCH + c) * 192 + t] = m;
}

// ---------------- pool pass 2: reduce partials + gather CITSEG ---------------------
__global__ __launch_bounds__(192) void pool_reduce_kernel(const float* __restrict__ hs) {
    int b = blockIdx.x;
    int t = threadIdx.x;

    const float4* pm = (const float4*)g_pmax + (size_t)b * PCH * 192;
    float4 m = pm[t];
    #pragma unroll
    for (int c = 1; c < PCH; c++) m = fmax4(m, pm[(size_t)c * 192 + t]);
    if (!g_keepany[b]) m = make_float4(0.f, 0.f, 0.f, 0.f);

    int h = t * 4;
    float mv[4] = {m.x, m.y, m.z, m.w};
    #pragma unroll
    for (int j = 0; j < 4; j++) {
        __nv_bfloat16 hi, lo;
        split_bf16(mv[j], hi, lo);
        g_x_hi[b * KP_X + h + j] = hi;
        g_x_lo[b * KP_X + h + j] = lo;
    }

    float4 cvec = ((const float4*)(hs + (size_t)b * S * H))[(size_t)g_cpos[b] * 192 + t];
    float cv[4] = {cvec.x, cvec.y, cvec.z, cvec.w};
    #pragma unroll
    for (int j = 0; j < 4; j++) {
        __nv_bfloat16 hi, lo;
        split_bf16(cv[j], hi, lo);
        g_cith_hi[b * KP_H + h + j] = hi;
        g_cith_lo[b * KP_H + h + j] = lo;
    }
}

// ---------------- zero padding columns of activation buffers -----------------------
__global__ void pad_zero_kernel() {
    int b = blockIdx.x;
    int t = threadIdx.x;  // 64
    __nv_bfloat16 z = __float2bfloat16(0.f);
    for (int c = t; c < KP_CIT - CIT; c += 64) {
        g_cit_hi[b * KP_CIT + CIT + c] = z;
        g_cit_lo[b * KP_CIT + CIT + c] = z;
    }
    for (int c = t; c < KP_X - XD; c += 64) {
        g_x_hi[b * KP_X + XD + c] = z;
        g_x_lo[b * KP_X + XD + c] = z;
    }
    for (int c = t; c < KP_D2 - D2; c += 64) {
        g_h1_hi[b * KP_D2 + D2 + c] = z;
        g_h1_lo[b * KP_D2 + D2 + c] = z;
    }
}

// ---------------- weight convert: W[K,N] fp32 -> [Kpad][Npad] hi/lo ------------------
__global__ void convert_pad_kernel(const float* __restrict__ W,
                                   __nv_bfloat16* __restrict__ Oh,
                                   __nv_bfloat16* __restrict__ Ol,
                                   int K, int N, int Npad, int total4)
{
    int idx = blockIdx.x * 256 + threadIdx.x;
    if (idx >= total4) return;
    int npc = Npad >> 2;
    int k  = idx / npc;
    int nc = (idx - k * npc) << 2;
    float v[4];
    if (k < K && nc + 3 < N) {
        const float* p = W + (size_t)k * N + nc;
        v[0] = p[0]; v[1] = p[1]; v[2] = p[2]; v[3] = p[3];
    } else {
        #pragma unroll
        for (int j = 0; j < 4; j++)
            v[j] = (k < K && nc + j < N) ? W[(size_t)k * N + nc + j] : 0.f;
    }
    __nv_bfloat16 hi[4], lo[4];
    #pragma unroll
    for (int j = 0; j < 4; j++) split_bf16(v[j], hi[j], lo[j]);
    size_t o = (size_t)k * Npad + nc;
    *(__nv_bfloat162*)(Oh + o)     = *(__nv_bfloat162*)&hi[0];
    *(__nv_bfloat162*)(Oh + o + 2) = *(__nv_bfloat162*)&hi[2];
    *(__nv_bfloat162*)(Ol + o)     = *(__nv_bfloat162*)&lo[0];
    *(__nv_bfloat162*)(Ol + o + 2) = *(__nv_bfloat162*)&lo[2];
}

// ---------------- split-bf16 ldmatrix GEMM ------------------------------------------
#define BM 64
#define BN 64
#define BK 64
#define BKP 72
#define BNP 72

#define SA_ELEMS (2 * 64 * BKP)
#define SB_ELEMS (2 * 64 * BNP)
#define GEMM_SMEM_BYTES ((SA_ELEMS * 2 + SB_ELEMS * 2) * 2)

__global__ __launch_bounds__(256, 2) void gemm_bf16_kernel(
    const __nv_bfloat16* __restrict__ Ah, const __nv_bfloat16* __restrict__ Al, int Kp,
    const __nv_bfloat16* __restrict__ Bh, const __nv_bfloat16* __restrict__ Bl, int Np,
    const float* __restrict__ bias, int N,
    float* Cf, int ldc,
    __nv_bfloat16* Ch, __nv_bfloat16* Cl, int ldcp,
    int relu, int scale_hasc)
{
    extern __shared__ __nv_bfloat16 sm[];

    int tid  = threadIdx.x;
    int lane = tid & 31;
    int warp = tid >> 5;
    int warpM = warp >> 2;
    int warpN = warp & 3;
    int g = lane >> 2;
    int t = lane & 3;

    int rowBase = blockIdx.y * BM;
    int colBase = blockIdx.x * BN;

    int ldRow0 = tid >> 3;
    int ldCol  = (tid & 7) * 8;
    const __nv_bfloat16* pAh = Ah + (size_t)(rowBase + ldRow0) * Kp + ldCol;
    const __nv_bfloat16* pAl = Al + (size_t)(rowBase + ldRow0) * Kp + ldCol;
    const __nv_bfloat16* pBh = Bh + (size_t)ldRow0 * Np + colBase + ldCol;
    const __nv_bfloat16* pBl = Bl + (size_t)ldRow0 * Np + colBase + ldCol;
    size_t aRowStep = (size_t)32 * Kp;
    size_t bRowStep = (size_t)32 * Np;

    uint32_t base_u32 = smem_u32(sm);
    uint32_t offAl = SA_ELEMS * 2;
    uint32_t offBh = SA_ELEMS * 4;
    uint32_t offBl = SA_ELEMS * 4 + SB_ELEMS * 2;
    uint32_t dAh0 = base_u32 + (ldRow0 * BKP + ldCol) * 2;
    uint32_t dB0  = base_u32 + offBh + (ldRow0 * BNP + ldCol) * 2;

    float acc[2][2][4] = {};

    int nk = Kp / BK;

    {
        #pragma unroll
        for (int i = 0; i < 2; i++) {
            uint32_t sa = dAh0 + i * 32 * BKP * 2;
            uint32_t sb = dB0  + i * 32 * BNP * 2;
            CP_ASYNC16(sa,          pAh + i * aRowStep);
            CP_ASYNC16(sa + offAl,  pAl + i * aRowStep);
            CP_ASYNC16(sb,          pBh + i * bRowStep);
            CP_ASYNC16(sb + (SB_ELEMS * 2), pBl + i * bRowStep);
        }
    }
    CP_COMMIT();

    for (int it = 0; it < nk; it++) {
        int cur = it & 1;
        if (it + 1 < nk) {
            int nxt = cur ^ 1;
            size_t ka = (size_t)(it + 1) * BK;
            uint32_t stA = nxt * 64 * BKP * 2;
            uint32_t stB = nxt * 64 * BNP * 2;
            #pragma unroll
            for (int i = 0; i < 2; i++) {
                uint32_t sa = dAh0 + stA + i * 32 * BKP * 2;
                uint32_t sb = dB0  + stB + i * 32 * BNP * 2;
                CP_ASYNC16(sa,          pAh + ka + i * aRowStep);
                CP_ASYNC16(sa + offAl,  pAl + ka + i * aRowStep);
                CP_ASYNC16(sb,          pBh + ka * Np + i * bRowStep);
                CP_ASYNC16(sb + (SB_ELEMS * 2), pBl + ka * Np + i * bRowStep);
            }
        }
        CP_COMMIT();
        CP_WAIT1();
        __syncthreads();

        uint32_t stA = cur * 64 * BKP * 2;
        uint32_t stB = cur * 64 * BNP * 2;

        #pragma unroll
        for (int ks = 0; ks < BK; ks += 16) {
            uint32_t ahi[2][4], alo[2][4], bhi[4], blo[4];
            #pragma unroll
            for (int mi = 0; mi < 2; mi++) {
                int arow = warpM * 32 + mi * 16 + (lane & 15);
                int acol = ks + (lane >> 4) * 8;
                uint32_t ea = stA + (arow * BKP + acol) * 2;
                LDSM_X4(ahi[mi], base_u32 + ea);
                LDSM_X4(alo[mi], base_u32 + offAl + ea);
            }
            {
                int mm = lane >> 3;
                int krow = ks + (mm & 1) * 8 + (lane & 7);
                int ncol = warpN * 16 + (mm >> 1) * 8;
                uint32_t eb = stB + (krow * BNP + ncol) * 2;
                LDSM_X4_T(bhi, base_u32 + offBh + eb);
                LDSM_X4_T(blo, base_u32 + offBl + eb);
            }
            #pragma unroll
            for (int mi = 0; mi < 2; mi++) {
                MMA_BF16(acc[mi][0], ahi[mi], bhi[0], bhi[1]);
                MMA_BF16(acc[mi][0], ahi[mi], blo[0], blo[1]);
                MMA_BF16(acc[mi][0], alo[mi], bhi[0], bhi[1]);
                MMA_BF16(acc[mi][1], ahi[mi], bhi[2], bhi[3]);
                MMA_BF16(acc[mi][1], ahi[mi], blo[2], blo[3]);
                MMA_BF16(acc[mi][1], alo[mi], bhi[2], bhi[3]);
            }
        }
        __syncthreads();
    }

    #pragma unroll
    for (int mi = 0; mi < 2; mi++) {
        #pragma unroll
        for (int ni = 0; ni < 2; ni++) {
            #pragma unroll
            for (int f = 0; f < 4; f++) {
                int gm = rowBase + warpM * 32 + mi * 16 + g + (f >= 2 ? 8 : 0);
                int gn = colBase + warpN * 16 + ni * 8 + 2 * t + (f & 1);
                if (gn < N) {
                    float sc = scale_hasc ? (float)g_hasc[gm] : 1.f;
                    float v = (acc[mi][ni][f] + bias[gn]) * sc;
                    if (relu) v = fmaxf(v, 0.f);
                    if (Cf) Cf[(size_t)gm * ldc + gn] = v;
                    if (Ch) {
                        __nv_bfloat16 hi, lo;
                        split_bf16(v, hi, lo);
                        Ch[(size_t)gm * ldcp + gn] = hi;
                        Cl[(size_t)gm * ldcp + gn] = lo;
                    }
                }
            }
        }
    }
}

// ---------------- head: out = h2 @ w3 + b3, N=6 ------------------------------------
__global__ void head_kernel(const float* __restrict__ w3,
                            const float* __restrict__ b3,
                            float* __restrict__ out)
{
    int b = blockIdx.x;
    int tid = threadIdx.x;  // 256
    float acc[NC] = {};
    for (int k = tid; k < D2; k += 256) {
        float a = g_h2[b * D2 + k];
        #pragma unroll
        for (int n = 0; n < NC; n++) acc[n] = fmaf(a, w3[k * NC + n], acc[n]);
    }
    __shared__ float sh[NC * 256];
    #pragma unroll
    for (int n = 0; n < NC; n++) sh[n * 256 + tid] = acc[n];
    __syncthreads();
    for (int off = 128; off > 0; off >>= 1) {
        if (tid < off) {
            #pragma unroll
            for (int n = 0; n < NC; n++)
                sh[n * 256 + tid] += sh[n * 256 + tid + off];
        }
        __syncthreads();
    }
    if (tid < NC) out[b * NC + tid] = sh[tid * 256] + b3[tid];
}

// ---------------- launch -------------------------------------------------------------
extern "C" void kernel_launch(void* const* d_in, const int* in_sizes, int n_in,
                              void* d_out, int out_size)
{
    const int*   tokens = (const int*)  d_in[0];
    const float* hs     = (const float*)d_in[1];
    const float* proj_w = (const float*)d_in[2];
    const float* proj_b = (const float*)d_in[3];
    const float* enc_w  = (const float*)d_in[4];
    const float* enc_b  = (const float*)d_in[5];
    const float* w1     = (const float*)d_in[6];
    const float* b1     = (const float*)d_in[7];
    const float* w2     = (const float*)d_in[8];
    const float* b2     = (const float*)d_in[9];
    const float* w3     = (const float*)d_in[10];
    const float* b3     = (const float*)d_in[11];
    float* out = (float*)d_out;

    __nv_bfloat16 *projw_h, *projw_l, *encw_h, *encw_l, *w1_h, *w1_l, *w2_h, *w2_l;
    __nv_bfloat16 *cith_h, *cith_l, *cit_h, *cit_l, *x_h, *x_l, *h1_h, *h1_l;
    float* h2;
    cudaGetSymbolAddress((void**)&projw_h, g_projw_hi);
    cudaGetSymbolAddress((void**)&projw_l, g_projw_lo);
    cudaGetSymbolAddress((void**)&encw_h,  g_encw_hi);
    cudaGetSymbolAddress((void**)&encw_l,  g_encw_lo);
    cudaGetSymbolAddress((void**)&w1_h,    g_w1_hi);
    cudaGetSymbolAddress((void**)&w1_l,    g_w1_lo);
    cudaGetSymbolAddress((void**)&w2_h,    g_w2_hi);
    cudaGetSymbolAddress((void**)&w2_l,    g_w2_lo);
    cudaGetSymbolAddress((void**)&cith_h,  g_cith_hi);
    cudaGetSymbolAddress((void**)&cith_l,  g_cith_lo);
    cudaGetSymbolAddress((void**)&cit_h,   g_cit_hi);
    cudaGetSymbolAddress((void**)&cit_l,   g_cit_lo);
    cudaGetSymbolAddress((void**)&x_h,     g_x_hi);
    cudaGetSymbolAddress((void**)&x_l,     g_x_lo);
    cudaGetSymbolAddress((void**)&h1_h,    g_h1_hi);
    cudaGetSymbolAddress((void**)&h1_l,    g_h1_lo);
    cudaGetSymbolAddress((void**)&h2,      g_h2);

    static bool init_done = false;
    static cudaStream_t sW = nullptr;
    static cudaEvent_t evFork = nullptr, evJoin = nullptr;
    if (!init_done) {
        cudaFuncSetAttribute(gemm_bf16_kernel,
                             cudaFuncAttributeMaxDynamicSharedMemorySize, GEMM_SMEM_BYTES);
        cudaStreamCreateWithFlags(&sW, cudaStreamNonBlocking);
        cudaEventCreateWithFlags(&evFork, cudaEventDisableTiming);
        cudaEventCreateWithFlags(&evJoin, cudaEventDisableTiming);
        init_done = true;
    }

    // ---- fork: weight converts on side stream (overlap with token path) ----
    cudaEventRecord(evFork, 0);
    cudaStreamWaitEvent(sW, evFork, 0);
    {
        int t4 = KP_H * NP_CIT / 4;
        convert_pad_kernel<<<(t4 + 255) / 256, 256, 0, sW>>>(proj_w, projw_h, projw_l, H, CIT, NP_CIT, t4);
        t4 = KP_CIT * NP_CIT / 4;
        convert_pad_kernel<<<(t4 + 255) / 256, 256, 0, sW>>>(enc_w, encw_h, encw_l, CIT, CIT, NP_CIT, t4);
        t4 = KP_X * NP_D2 / 4;
        convert_pad_kernel<<<(t4 + 255) / 256, 256, 0, sW>>>(w1, w1_h, w1_l, XD, D2, NP_D2, t4);
        t4 = KP_D2 * NP_D2 / 4;
        convert_pad_kernel<<<(t4 + 255) / 256, 256, 0, sW>>>(w2, w2_h, w2_l, D2, D2, NP_D2, t4);
    }
    cudaEventRecord(evJoin, sW);

    // ---- token path on main stream ----
    scan_kernel<<<B, 512>>>(tokens);
    pad_zero_kernel<<<B, 64>>>();
    pool_partial_kernel<<<dim3(B, PCH), 192>>>(hs);
    pool_reduce_kernel<<<B, 192>>>(hs);

    // ---- join before GEMMs ----
    cudaStreamWaitEvent(0, evJoin, 0);

    gemm_bf16_kernel<<<dim3(NP_CIT / BN, B / BM), 256, GEMM_SMEM_BYTES>>>(
        cith_h, cith_l, KP_H, projw_h, projw_l, NP_CIT, proj_b, CIT,
        nullptr, 0, cit_h, cit_l, KP_CIT, 0, 1);

    gemm_bf16_kernel<<<dim3(NP_CIT / BN, B / BM), 256, GEMM_SMEM_BYTES>>>(
        cit_h, cit_l, KP_CIT, encw_h, encw_l, NP_CIT, enc_b, CIT,
        nullptr, 0, x_h + H, x_l + H, KP_X, 0, 0);

    gemm_bf16_kernel<<<dim3(NP_D2 / BN, B / BM), 256, GEMM_SMEM_BYTES>>>(
        x_h, x_l, KP_X, w1_h, w1_l, NP_D2, b1, D2,
        nullptr, 0, h1_h, h1_l, KP_D2, 1, 0);

    gemm_bf16_kernel<<<dim3(NP_D2 / BN, B / BM), 256, GEMM_SMEM_BYTES>>>(
        h1_h, h1_l, KP_D2, w2_h, w2_l, NP_D2, b2, D2,
        h2, D2, nullptr, nullptr, 0, 1, 0);

    head_kernel<<<B, 256>>>(w3, b3, out);
}